// round 7
// baseline (speedup 1.0000x reference)
#include <cuda_runtime.h>
#include <cuda_fp16.h>
#include <cstdint>

typedef unsigned int u32;

#define H 256
#define W 256
#define RAD 5
#define KS 11
#define PLANE (H*W)

#define TW 32
#define TH 8
#define NTEAM 2
#define HLW (TW + 2*RAD)   // 42
#define HLH (TH + 2*RAD)   // 18
#define SSTR 43            // padded row stride
#define NS (HLH * SSTR)    // 774

__device__ __forceinline__ u32 pk(float a, float b) {
    __half2 h = __floats2half2_rn(a, b);
    return *reinterpret_cast<u32*>(&h);
}
__device__ __forceinline__ __half2 uh(u32 u) {
    return *reinterpret_cast<__half2*>(&u);
}

__global__ __launch_bounds__(512, 2) void jbf_kernel(
    const float* __restrict__ img, const float* __restrict__ gui,
    const float* __restrict__ est, const float* __restrict__ var,
    const float* __restrict__ sig, float* __restrict__ out, float K)
{
    // sG packing (per pixel, 4 half2 words), STRONG channels first so the
    // row-skip test needs only the first 8 bytes (one aligned LDS.64):
    //   word0 = (g2,g3)*sqrt(50*EXS), word1 = (g4*sqrt(50*EXS), g5*sqrt(10*EXS))
    //   word2 = (g0,g1)*sqrt(0.1*EXS), word3 = (g6,g7)*sqrt(10*EXS)
    __shared__ uint4  sG[NS];
    __shared__ uint4  sMR[NS];   // {h2(e0,e1), h2(Kv0,Kv1), h2(Kv2,e2), img2 bits}
    __shared__ float2 sI2[NS];   // img ch0, ch1 (fp32)
    __shared__ float4 sRed[TH * TW];

    const int bx = blockIdx.x * TW, by = blockIdx.y * TH;
    const int tx = threadIdx.x, ty = threadIdx.y, tz = threadIdx.z;
    const int tid = tx + TW * (ty + TH * tz);

    // fold -0.5*log2(e) of the exp into the guidance prescale
    const float EXS = 0.72134752044f;
    const float rs0 = sqrtf(sig[0]  * EXS), rs1 = sqrtf(sig[9]  * EXS);
    const float rs2 = sqrtf(sig[18] * EXS), rs3 = sqrtf(sig[27] * EXS);
    const float rs4 = sqrtf(sig[36] * EXS), rs5 = sqrtf(sig[45] * EXS);
    const float rs6 = sqrtf(sig[54] * EXS), rs7 = sqrtf(sig[63] * EXS);

    // Fused halo fill with reflect padding
    for (int i = tid; i < HLW * HLH; i += TW * TH * NTEAM) {
        int r = i / HLW, c = i - r * HLW;
        int gy = by + r - RAD, gx = bx + c - RAD;
        gy = (gy < 0) ? -gy : ((gy > H - 1) ? 2 * (H - 1) - gy : gy);
        gx = (gx < 0) ? -gx : ((gx > W - 1) ? 2 * (W - 1) - gx : gx);
        const int s = gy * W + gx;
        const int si = r * SSTR + c;

        uint4 g;
        g.x = pk(gui[s + 2*PLANE] * rs2, gui[s + 3*PLANE] * rs3);  // strong
        g.y = pk(gui[s + 4*PLANE] * rs4, gui[s + 5*PLANE] * rs5);  // strong
        g.z = pk(gui[s]           * rs0, gui[s +   PLANE] * rs1);
        g.w = pk(gui[s + 6*PLANE] * rs6, gui[s + 7*PLANE] * rs7);
        sG[si] = g;

        const float e0 = est[s], e1 = est[s + PLANE], e2 = est[s + 2*PLANE];
        const float v0 = K * var[s], v1 = K * var[s + PLANE], v2 = K * var[s + 2*PLANE];
        uint4 mr;
        mr.x = pk(e0, e1);
        mr.y = pk(v0, v1);
        mr.z = pk(v2, e2);                                        // ch2: e2 in HIGH half
        mr.w = *reinterpret_cast<const u32*>(&img[s + 2*PLANE]);  // img ch2 bits
        sMR[si] = mr;

        float2 i2; i2.x = img[s]; i2.y = img[s + PLANE];
        sI2[si] = i2;
    }
    __syncthreads();

    const int cidx = (ty + RAD) * SSTR + (tx + RAD);
    const uint4 cg = sG[cidx];
    const __half2 cg0 = uh(cg.x), cg1 = uh(cg.y), cg2 = uh(cg.z), cg3 = uh(cg.w);
    const uint4 cmr = sMR[cidx];
    const __half2 cP = uh(cmr.x), cR = uh(cmr.y), cQ = uh(cmr.z);

    const __half thr = __float2half(30.0f);

    float a0 = 0.f, a1 = 0.f, a2 = 0.f, ws = 0.f;

    // Team tz handles dy = tz, tz+2, ...
    for (int dy = tz; dy < KS; dy += NTEAM) {
        const int base = (ty + dy) * SSTR + tx;

        // ---- Fast row test: partial (strong-channel) mahal for all 11 taps,
        //      batched LDS.64, one min-reduce, ONE vote+branch per row.
        //      partial <= full mahal, so skipping on partial>thr is sound;
        //      center & duplicate taps give partial==0 -> row goes slow.
        __half2 mm[5]; __half m10;
#pragma unroll
        for (int j = 0; j < 5; j++) {
            const uint2 ga = *reinterpret_cast<const uint2*>(&sG[base + 2*j]);
            const uint2 gb = *reinterpret_cast<const uint2*>(&sG[base + 2*j + 1]);
            __half2 da = __hsub2(cg0, uh(ga.x));
            __half2 pa = __hmul2(da, da);
            da = __hsub2(cg1, uh(ga.y));
            pa = __hfma2(da, da, pa);
            __half2 db = __hsub2(cg0, uh(gb.x));
            __half2 pb = __hmul2(db, db);
            db = __hsub2(cg1, uh(gb.y));
            pb = __hfma2(db, db, pb);
            mm[j] = __halves2half2(__hadd(__low2half(pa), __high2half(pa)),
                                   __hadd(__low2half(pb), __high2half(pb)));
        }
        {
            const uint2 ga = *reinterpret_cast<const uint2*>(&sG[base + 10]);
            __half2 da = __hsub2(cg0, uh(ga.x));
            __half2 pa = __hmul2(da, da);
            da = __hsub2(cg1, uh(ga.y));
            pa = __hfma2(da, da, pa);
            m10 = __hadd(__low2half(pa), __high2half(pa));
        }
        __half2 mn2 = __hmin2(__hmin2(mm[0], mm[1]), __hmin2(mm[2], mm[3]));
        mn2 = __hmin2(mn2, mm[4]);
        const __half mn = __hmin(__hmin(__low2half(mn2), __high2half(mn2)), m10);
        if (__all_sync(0xFFFFFFFFu, __hgt(mn, thr))) continue;

        // ---- Slow path (rare): full evaluation of the 11 taps.
#pragma unroll 1
        for (int dx = 0; dx < KS; dx++) {
            const int n = base + dx;

            const uint4 ng = sG[n];
            __half2 d, m2;
            d  = __hsub2(cg0, uh(ng.x)); m2 = __hmul2(d, d);
            d  = __hsub2(cg1, uh(ng.y)); m2 = __hfma2(d, d, m2);
            d  = __hsub2(cg2, uh(ng.z)); m2 = __hfma2(d, d, m2);
            d  = __hsub2(cg3, uh(ng.w)); m2 = __hfma2(d, d, m2);
            const float m = __half2float(__hadd(__low2half(m2), __high2half(m2)));

            float bl;
            {
                const float p = -m;
                asm("ex2.approx.ftz.f32 %0, %1;" : "=f"(bl) : "f"(p));
            }

            // Membership: d_c^2 < K*(v_ci + v_cj), 3 channels (== t < gamma_w)
            const uint4 nmr = sMR[n];
            const __half2 nP = uh(nmr.x), nR = uh(nmr.y), nQ = uh(nmr.z);
            const __half2 d01 = __hsub2(cP, nP);
            const __half2 s01 = __hadd2(cR, nR);
            const __half2 r01 = __hfma2(d01, d01, __hneg2(s01));           // signs @15,@31
            const __half2 dq  = __hsub2(cQ, nQ);                           // {dKv2, d_e2}
            const __half2 sq  = __hadd2(cQ, nQ);                           // {sKv2, ...}
            const __half2 r2h = __hfma2(dq, dq, __hneg2(__low2half2(sq))); // sign @31
            const u32 u01 = *reinterpret_cast<const u32*>(&r01);
            const u32 u2  = *reinterpret_cast<const u32*>(&r2h);
            const u32 allneg = u01 & (u01 << 16) & u2;

            u32 mask = (u32)((int)allneg >> 31);
            u32 wb = (*reinterpret_cast<const u32*>(&bl)) & mask;
            float w = *reinterpret_cast<const float*>(&wb);
            if (dx == RAD && dy == RAD) w = 1.0f;   // center forced to 1

            const float2 im = sI2[n];
            ws += w;
            a0 = fmaf(w, im.x, a0);
            a1 = fmaf(w, im.y, a1);
            a2 = fmaf(w, *reinterpret_cast<const float*>(&nmr.w), a2);
        }
    }

    // Cross-team reduction
    if (tz == 1) {
        float4 p; p.x = a0; p.y = a1; p.z = a2; p.w = ws;
        sRed[ty * TW + tx] = p;
    }
    __syncthreads();
    if (tz == 0) {
        const float4 p = sRed[ty * TW + tx];
        a0 += p.x; a1 += p.y; a2 += p.z; ws += p.w;

        const float inv = 1.0f / fmaxf(ws, 1e-10f);
        const int o = (by + ty) * W + (bx + tx);
        out[o]           = a0 * inv;
        out[PLANE + o]   = a1 * inv;
        out[2*PLANE + o] = a2 * inv;
    }
}

extern "C" void kernel_launch(void* const* d_in, const int* in_sizes, int n_in,
                              void* d_out, int out_size) {
    const float* img = (const float*)d_in[0];   // [3,256,256]
    const float* gui = (const float*)d_in[1];   // [8,256,256]
    const float* est = (const float*)d_in[2];   // [3,256,256]
    const float* var = (const float*)d_in[3];   // [3,256,256]
    const float* sig = (const float*)d_in[4];   // [8,8]
    (void)in_sizes; (void)n_in;

    // membership: t < gamma  <=>  d^2 < gamma^2 * (vi+vj)
    const float K = 2.9110f * 2.9110f;

    dim3 block(TW, TH, NTEAM);          // 512 threads
    dim3 grid(W / TW, H / TH);          // 8 x 32 = 256 CTAs
    jbf_kernel<<<grid, block>>>(img, gui, est, var, sig, (float*)d_out, K);
}

// round 8
// speedup vs baseline: 1.4117x; 1.4117x over previous
#include <cuda_runtime.h>
#include <cuda_fp16.h>
#include <cstdint>

typedef unsigned int u32;

#define H 256
#define W 256
#define RAD 5
#define KS 11
#define PLANE (H*W)

#define TW 32
#define TH 8
#define NTEAM 3
#define HLW (TW + 2*RAD)   // 42
#define HLH (TH + 2*RAD)   // 18
#define SSTR 43            // padded row stride
#define NS (HLH * SSTR)    // 774

__device__ __forceinline__ u32 pk(float a, float b) {
    __half2 h = __floats2half2_rn(a, b);
    return *reinterpret_cast<u32*>(&h);
}
__device__ __forceinline__ __half2 uh(u32 u) {
    return *reinterpret_cast<__half2*>(&u);
}

__global__ __launch_bounds__(768, 2) void jbf_kernel(
    const float* __restrict__ img, const float* __restrict__ gui,
    const float* __restrict__ est, const float* __restrict__ var,
    const float* __restrict__ sig, float* __restrict__ out, float K)
{
    // SoA halo: fast path touches only sG (1 LDS.128 / eval)
    __shared__ uint4  sG[NS];    // 8 guidance halves, prescaled by sqrt(0.7213*sig_inv)
    __shared__ uint4  sMR[NS];   // {h2(e0,e1), h2(Kv0,Kv1), h2(Kv2,e2), img2 bits}
    __shared__ float2 sI2[NS];   // img ch0, ch1 (fp32)
    __shared__ float4 sRed[NTEAM - 1][TH * TW];

    const int bx = blockIdx.x * TW, by = blockIdx.y * TH;
    const int tx = threadIdx.x, ty = threadIdx.y, tz = threadIdx.z;
    const int tid = tx + TW * (ty + TH * tz);

    // fold -0.5*log2(e) of the exp into the guidance prescale
    const float EXS = 0.72134752044f;
    const float rs0 = sqrtf(sig[0]  * EXS), rs1 = sqrtf(sig[9]  * EXS);
    const float rs2 = sqrtf(sig[18] * EXS), rs3 = sqrtf(sig[27] * EXS);
    const float rs4 = sqrtf(sig[36] * EXS), rs5 = sqrtf(sig[45] * EXS);
    const float rs6 = sqrtf(sig[54] * EXS), rs7 = sqrtf(sig[63] * EXS);

    // Fused halo fill with reflect padding (756 halo px, 768 threads: 1 pass)
    for (int i = tid; i < HLW * HLH; i += TW * TH * NTEAM) {
        int r = i / HLW, c = i - r * HLW;
        int gy = by + r - RAD, gx = bx + c - RAD;
        gy = (gy < 0) ? -gy : ((gy > H - 1) ? 2 * (H - 1) - gy : gy);
        gx = (gx < 0) ? -gx : ((gx > W - 1) ? 2 * (W - 1) - gx : gx);
        const int s = gy * W + gx;
        const int si = r * SSTR + c;

        uint4 g;
        g.x = pk(gui[s]           * rs0, gui[s +   PLANE] * rs1);
        g.y = pk(gui[s + 2*PLANE] * rs2, gui[s + 3*PLANE] * rs3);
        g.z = pk(gui[s + 4*PLANE] * rs4, gui[s + 5*PLANE] * rs5);
        g.w = pk(gui[s + 6*PLANE] * rs6, gui[s + 7*PLANE] * rs7);
        sG[si] = g;

        const float e0 = est[s], e1 = est[s + PLANE], e2 = est[s + 2*PLANE];
        const float v0 = K * var[s], v1 = K * var[s + PLANE], v2 = K * var[s + 2*PLANE];
        uint4 mr;
        mr.x = pk(e0, e1);
        mr.y = pk(v0, v1);
        mr.z = pk(v2, e2);                                        // ch2: e2 in HIGH half
        mr.w = *reinterpret_cast<const u32*>(&img[s + 2*PLANE]);  // img ch2 bits
        sMR[si] = mr;

        float2 i2; i2.x = img[s]; i2.y = img[s + PLANE];
        sI2[si] = i2;
    }
    __syncthreads();

    const int cidx = (ty + RAD) * SSTR + (tx + RAD);
    const uint4 cg = sG[cidx];
    const __half2 cg0 = uh(cg.x), cg1 = uh(cg.y), cg2 = uh(cg.z), cg3 = uh(cg.w);
    const uint4 cmr = sMR[cidx];
    const __half2 cP = uh(cmr.x), cR = uh(cmr.y), cQ = uh(cmr.z);

    const __half thr = __float2half(30.0f);

    float a0 = 0.f, a1 = 0.f, a2 = 0.f, ws = 0.f;

    // Team tz handles dy = tz, tz+3, ... (teams 0,1: 4 rows; team 2: 3 rows)
    for (int dy = tz; dy < KS; dy += NTEAM) {
        const int base = (ty + dy) * SSTR + tx;
#pragma unroll
        for (int dx = 0; dx < KS; dx++) {
            const int n = base + dx;

            // 0.7213 * Mahalanobis in packed fp16 (prescaled guidance)
            const uint4 ng = sG[n];
            __half2 d, m2;
            d  = __hsub2(cg0, uh(ng.x)); m2 = __hmul2(d, d);
            d  = __hsub2(cg1, uh(ng.y)); m2 = __hfma2(d, d, m2);
            d  = __hsub2(cg2, uh(ng.z)); m2 = __hfma2(d, d, m2);
            d  = __hsub2(cg3, uh(ng.w)); m2 = __hfma2(d, d, m2);
            const __half mh = __hadd(__low2half(m2), __high2half(m2));

            // Early skip: bilateral = 2^-m < 2^-30 for every lane -> weight
            // numerically zero (fp32 reference also yields ~0). Center and
            // reflect-duplicate taps give m == 0 -> warp takes the slow path,
            // so the exact-weight cases are always fully evaluated.
            if (__all_sync(0xFFFFFFFFu, __hgt(mh, thr))) continue;

            const float m = __half2float(mh);
            float bl;
            {
                const float p = -m;
                asm("ex2.approx.ftz.f32 %0, %1;" : "=f"(bl) : "f"(p));
            }

            // Membership: d_c^2 < K*(v_ci + v_cj), 3 channels (== t < gamma_w)
            const uint4 nmr = sMR[n];
            const __half2 nP = uh(nmr.x), nR = uh(nmr.y), nQ = uh(nmr.z);
            const __half2 d01 = __hsub2(cP, nP);
            const __half2 s01 = __hadd2(cR, nR);
            const __half2 r01 = __hfma2(d01, d01, __hneg2(s01));           // signs @15,@31
            const __half2 dq  = __hsub2(cQ, nQ);                           // {dKv2, d_e2}
            const __half2 sq  = __hadd2(cQ, nQ);                           // {sKv2, ...}
            const __half2 r2h = __hfma2(dq, dq, __hneg2(__low2half2(sq))); // sign @31
            const u32 u01 = *reinterpret_cast<const u32*>(&r01);
            const u32 u2  = *reinterpret_cast<const u32*>(&r2h);
            const u32 allneg = u01 & (u01 << 16) & u2;

            u32 mask = (u32)((int)allneg >> 31);
            u32 wb = (*reinterpret_cast<const u32*>(&bl)) & mask;
            float w = *reinterpret_cast<const float*>(&wb);
            if (dx == RAD) w = (dy == RAD) ? 1.0f : w;   // center forced to 1

            const float2 im = sI2[n];
            ws += w;
            a0 = fmaf(w, im.x, a0);
            a1 = fmaf(w, im.y, a1);
            a2 = fmaf(w, *reinterpret_cast<const float*>(&nmr.w), a2);
        }
    }

    // Cross-team reduction (teams 1..NTEAM-1 -> team 0)
    if (tz > 0) {
        float4 p; p.x = a0; p.y = a1; p.z = a2; p.w = ws;
        sRed[tz - 1][ty * TW + tx] = p;
    }
    __syncthreads();
    if (tz == 0) {
        const float4 p = sRed[0][ty * TW + tx];
        const float4 q = sRed[1][ty * TW + tx];
        a0 += p.x + q.x; a1 += p.y + q.y; a2 += p.z + q.z; ws += p.w + q.w;

        const float inv = 1.0f / fmaxf(ws, 1e-10f);
        const int o = (by + ty) * W + (bx + tx);
        out[o]           = a0 * inv;
        out[PLANE + o]   = a1 * inv;
        out[2*PLANE + o] = a2 * inv;
    }
}

extern "C" void kernel_launch(void* const* d_in, const int* in_sizes, int n_in,
                              void* d_out, int out_size) {
    const float* img = (const float*)d_in[0];   // [3,256,256]
    const float* gui = (const float*)d_in[1];   // [8,256,256]
    const float* est = (const float*)d_in[2];   // [3,256,256]
    const float* var = (const float*)d_in[3];   // [3,256,256]
    const float* sig = (const float*)d_in[4];   // [8,8]
    (void)in_sizes; (void)n_in;

    // membership: t < gamma  <=>  d^2 < gamma^2 * (vi+vj)
    const float K = 2.9110f * 2.9110f;

    dim3 block(TW, TH, NTEAM);          // 768 threads
    dim3 grid(W / TW, H / TH);          // 8 x 32 = 256 CTAs
    jbf_kernel<<<grid, block>>>(img, gui, est, var, sig, (float*)d_out, K);
}